// round 10
// baseline (speedup 1.0000x reference)
#include <cuda_runtime.h>
#include <math.h>

// SO3Reparameterize: fused triple-GEMV (65536x1024 @ 1024x9) + Rodrigues epilogue.
// R10 = R9 resubmit (R9 hit an infra flake, never ran):
// 1 row/thread -> 2048 warps (12 resident/SM) for latency hiding by warp
// multiplexing; warp-autonomous cp.async 3-stage rings (no block barrier in
// mainloop); transposed smem weights via broadcast LDS.128; fma.rn.f32x2;
// exact tail wait (wait_group 0 on last iteration) fixing the R8 race.

#define D_IN    1024
#define THREADS 128
#define TILE_R  128          // rows per block (1 per thread)
#define KC      16           // k-chunk
#define ROWPAD  20           // floats per staged row
#define NCHUNK  (D_IN / KC)  // 64
#define NPAIR   (D_IN / 2)   // 512
#define STAGES  3
#define WROWS   32                                   // rows per warp
#define WARP_FLOATS (WROWS * ROWPAD)                 // 640 floats = 2560 B
#define XS_FLOATS   (4 * WARP_FLOATS)                // per stage, 4 warps = 10240 B
#define SMEM_BYTES  (9 * NPAIR * 8 + STAGES * XS_FLOATS * 4)   // 36864+30720=67584

typedef unsigned long long u64;

__device__ __forceinline__ u64 pack2(float a, float b) {
    u64 r;
    asm("mov.b64 %0, {%1, %2};" : "=l"(r) : "r"(__float_as_uint(a)), "r"(__float_as_uint(b)));
    return r;
}
__device__ __forceinline__ void unpack2(u64 v, float& a, float& b) {
    unsigned lo, hi;
    asm("mov.b64 {%0, %1}, %2;" : "=r"(lo), "=r"(hi) : "l"(v));
    a = __uint_as_float(lo);
    b = __uint_as_float(hi);
}
__device__ __forceinline__ void ffma2(u64& acc, u64 x, u64 w) {
    asm("fma.rn.f32x2 %0, %1, %2, %0;" : "+l"(acc) : "l"(x), "l"(w));
}
__device__ __forceinline__ void cp_async16(unsigned saddr, const void* gptr) {
    asm volatile("cp.async.cg.shared.global [%0], [%1], 16;" :: "r"(saddr), "l"(gptr));
}
__device__ __forceinline__ void cp_commit() {
    asm volatile("cp.async.commit_group;");
}
__device__ __forceinline__ void cp_wait1() {
    asm volatile("cp.async.wait_group 1;");
}
__device__ __forceinline__ void cp_wait0() {
    asm volatile("cp.async.wait_group 0;");
}

__device__ __forceinline__ void rodrigues(float vx, float vy, float vz, float* R) {
    float th  = sqrtf(vx * vx + vy * vy + vz * vz);
    float inv = 1.0f / th;
    float ux = vx * inv, uy = vy * inv, uz = vz * inv;
    float s = sinf(th), c = cosf(th), C = 1.0f - c;
    R[0] = c + ux * ux * C;      R[1] = ux * uy * C - uz * s;  R[2] = ux * uz * C + uy * s;
    R[3] = uy * ux * C + uz * s; R[4] = c + uy * uy * C;       R[5] = uy * uz * C - ux * s;
    R[6] = uz * ux * C - uy * s; R[7] = uz * uy * C + ux * s;  R[8] = c + uz * uz * C;
}

__device__ __forceinline__ float softplus_stable(float t) {
    return fmaxf(t, 0.0f) + log1pf(expf(-fabsf(t)));
}

__global__ void __launch_bounds__(THREADS)
so3_kernel(const float* __restrict__ x, const float* __restrict__ eps,
           const float* __restrict__ Wmu, const float* __restrict__ bmu,
           const float* __restrict__ Wd,  const float* __restrict__ bd,
           const float* __restrict__ Wl,  const float* __restrict__ bl,
           float* __restrict__ out, int B, int n)
{
    extern __shared__ unsigned char smem_raw[];
    u64*   wpkT = (u64*)smem_raw;                         // [j][k2], 9*512 pairs
    float* xs   = (float*)(smem_raw + 9 * NPAIR * 8);     // [STAGES][4 warps][WROWS*ROWPAD]

    const int tid  = threadIdx.x;
    const int w    = tid >> 5;
    const int lane = tid & 31;
    const int row0 = blockIdx.x * TILE_R;

    // Warp w owns global rows row0 + w*32 + [0,32); this thread computes one row.
    const int row = row0 + w * 32 + lane;

    // Staging mapping within warp: 32 rows x 4 16B-quarters = 128 segs, 4/lane.
    const int a  = lane >> 2;
    const int cf = lane & 3;
    const unsigned sA = (unsigned)(w * WARP_FLOATS * 4 + (a * ROWPAD + cf * 4) * 4);
    int grA = row0 + w * 32 + a;   if (grA > B - 1) grA = B - 1;
    const float* gA = x + (size_t)grA * D_IN + cf * 4;

    const unsigned xs_base = (unsigned)__cvta_generic_to_shared(xs);

    // Prologue cp.async first so loads fly during weight staging.
#pragma unroll
    for (int s = 0; s < STAGES - 1; s++) {
        unsigned base = xs_base + (unsigned)(s * XS_FLOATS * 4);
        const float* pA = gA + s * KC;
#pragma unroll
        for (int i = 0; i < 4; i++)   // rows a + 8i
            cp_async16(base + sA + (unsigned)(i * 8 * ROWPAD * 4),
                       pA + (size_t)(8 * i) * D_IN);
        cp_commit();
    }

    // Stage weights transposed: wpkT[j*NPAIR + k2] = (W[2k2][c], W[2k2+1][c]).
    for (int i = tid; i < 9 * NPAIR; i += THREADS) {
        int j = i / NPAIR, k2 = i - j * NPAIR;
        const float* W;
        int c;
        if (j < 3)      { W = Wmu; c = j; }
        else if (j < 6) { W = Wd;  c = j - 3; }
        else            { W = Wl;  c = j - 6; }
        wpkT[i] = pack2(W[(2 * k2) * 3 + c], W[(2 * k2 + 1) * 3 + c]);
    }
    __syncthreads();   // weights visible; mainloop is barrier-free

    u64 acc[9];
#pragma unroll
    for (int j = 0; j < 9; j++) acc[j] = 0ull;

    int slot  = 0;                // per-warp ring state
    int pslot = STAGES - 1;

#pragma unroll 1
    for (int ch = 0; ch < NCHUNK; ch++) {
        // Chunk ch's group must be complete. For ch < NCHUNK-1 one newer group
        // (chunk ch+1) may stay in flight; at ch == NCHUNK-1 chunk ch's group
        // IS the newest -> drain fully. (wait_group 1 there was the R8 race.)
        if (ch < NCHUNK - 1) cp_wait1(); else cp_wait0();
        __syncwarp();

        if (ch + STAGES - 1 < NCHUNK) {
            unsigned base = xs_base + (unsigned)(pslot * XS_FLOATS * 4);
            const float* pA = gA + (ch + STAGES - 1) * KC;
#pragma unroll
            for (int i = 0; i < 4; i++)
                cp_async16(base + sA + (unsigned)(i * 8 * ROWPAD * 4),
                           pA + (size_t)(8 * i) * D_IN);
            cp_commit();
        }

        // Compute chunk ch from this warp's partition.
        const float* xra = xs + slot * XS_FLOATS + w * WARP_FLOATS + lane * ROWPAD;
        const u64*   wch = wpkT + ch * (KC / 2);
#pragma unroll
        for (int p = 0; p < KC / 4; p++) {                 // 4 quads
            ulonglong2 xav = *(const ulonglong2*)&xra[p * 4];
#pragma unroll
            for (int j = 0; j < 9; j++) {
                ulonglong2 wv = *(const ulonglong2*)&wch[j * NPAIR + 2 * p];  // broadcast
                ffma2(acc[j], xav.x, wv.x);
                ffma2(acc[j], xav.y, wv.y);
            }
        }

        slot  = (slot  + 1 == STAGES) ? 0 : slot  + 1;
        pslot = (pslot + 1 == STAGES) ? 0 : pslot + 1;
    }

    if (row >= B) return;

    // --- Epilogue ---
    float s[9];
#pragma unroll
    for (int j = 0; j < 9; j++) {
        float lo, hi;
        unpack2(acc[j], lo, hi);
        s[j] = lo + hi;
    }
    float m0 = s[0] + bmu[0], m1 = s[1] + bmu[1], m2 = s[2] + bmu[2];
    float sd0 = sqrtf(softplus_stable(s[3] + bd[0]));
    float sd1 = sqrtf(softplus_stable(s[4] + bd[1]));
    float sd2 = sqrtf(softplus_stable(s[5] + bd[2]));
    float l0 = s[6] + bl[0], l1 = s[7] + bl[1], l2 = s[8] + bl[2];

    float Rm[9];
    rodrigues(m0, m1, m2, Rm);

    for (int jn = 0; jn < n; jn++) {
        size_t base = (size_t)(jn * B + row) * 3;
        float e0 = eps[base + 0], e1 = eps[base + 1], e2 = eps[base + 2];
        float a0 = sd0 * e0, a1 = sd1 * e1, a2 = sd2 * e2;
        float v0 = a0;
        float v1 = l0 * a0 + a1;
        float v2 = l1 * a0 + l2 * a1 + a2;

        float Rv[9];
        rodrigues(v0, v1, v2, Rv);

        float* o = out + (size_t)(jn * B + row) * 9;
#pragma unroll
        for (int i = 0; i < 3; i++) {
#pragma unroll
            for (int k = 0; k < 3; k++) {
                o[i * 3 + k] = Rm[i * 3 + 0] * Rv[0 * 3 + k]
                             + Rm[i * 3 + 1] * Rv[1 * 3 + k]
                             + Rm[i * 3 + 2] * Rv[2 * 3 + k];
            }
        }
    }
}

extern "C" void kernel_launch(void* const* d_in, const int* in_sizes, int n_in,
                              void* d_out, int out_size)
{
    const float* x   = (const float*)d_in[0];
    const float* eps = (const float*)d_in[1];
    const float* Wmu = (const float*)d_in[2];
    const float* bmu = (const float*)d_in[3];
    const float* Wd  = (const float*)d_in[4];
    const float* bd  = (const float*)d_in[5];
    const float* Wl  = (const float*)d_in[6];
    const float* bl  = (const float*)d_in[7];

    const int B = in_sizes[0] / D_IN;
    const int n = in_sizes[1] / (B * 3);

    cudaFuncSetAttribute(so3_kernel, cudaFuncAttributeMaxDynamicSharedMemorySize, SMEM_BYTES);

    const int grid = (B + TILE_R - 1) / TILE_R;
    so3_kernel<<<grid, THREADS, SMEM_BYTES>>>(x, eps, Wmu, bmu, Wd, bd, Wl, bl,
                                              (float*)d_out, B, n);
}

// round 11
// speedup vs baseline: 1.1708x; 1.1708x over previous
#include <cuda_runtime.h>
#include <math.h>

// SO3Reparameterize: fused triple-GEMV (65536x1024 @ 1024x9) + Rodrigues epilogue.
// R11: k-split. Each row's k-range is split across two blocks (k-halves), each
// block keeps 2 rows/thread (the proven per-row instruction cost) and only its
// half of the weight table (18.4KB). Swizzled ROWPAD=16 staging shrinks smem to
// 67.6KB -> 3 blocks/SM -> 12 resident warps/SM at R7's total instruction
// count. Partial sums go to static __device__ scratch; a small second kernel
// combines halves and runs the Rodrigues epilogue.

#define D_IN    1024
#define THREADS 128
#define TILE_R  256          // rows per block (2 per thread)
#define KC      16           // k-chunk
#define KHALF   512          // k per block
#define NCHUNK  (KHALF / KC) // 32
#define HPAIR   256          // weight k-pairs per half
#define STAGES  3
#define WROWS   64                                   // rows per warp
#define WARP_FLOATS (WROWS * 16)                     // 1024 floats = 4096 B
#define XS_FLOATS   (4 * WARP_FLOATS)                // per stage = 16384 B
#define SMEM_BYTES  (9 * HPAIR * 8 + STAGES * XS_FLOATS * 4)  // 18432+49152=67584
#define MAXB    65536

typedef unsigned long long u64;

__device__ float g_scratch[2 * 9 * MAXB];            // [half][j][row] partials

__device__ __forceinline__ u64 pack2(float a, float b) {
    u64 r;
    asm("mov.b64 %0, {%1, %2};" : "=l"(r) : "r"(__float_as_uint(a)), "r"(__float_as_uint(b)));
    return r;
}
__device__ __forceinline__ void unpack2(u64 v, float& a, float& b) {
    unsigned lo, hi;
    asm("mov.b64 {%0, %1}, %2;" : "=r"(lo), "=r"(hi) : "l"(v));
    a = __uint_as_float(lo);
    b = __uint_as_float(hi);
}
__device__ __forceinline__ void ffma2(u64& acc, u64 x, u64 w) {
    asm("fma.rn.f32x2 %0, %1, %2, %0;" : "+l"(acc) : "l"(x), "l"(w));
}
__device__ __forceinline__ void cp_async16(unsigned saddr, const void* gptr) {
    asm volatile("cp.async.cg.shared.global [%0], [%1], 16;" :: "r"(saddr), "l"(gptr));
}
__device__ __forceinline__ void cp_commit() {
    asm volatile("cp.async.commit_group;");
}
__device__ __forceinline__ void cp_wait1() {
    asm volatile("cp.async.wait_group 1;");
}
__device__ __forceinline__ void cp_wait0() {
    asm volatile("cp.async.wait_group 0;");
}

__device__ __forceinline__ void rodrigues(float vx, float vy, float vz, float* R) {
    float th  = sqrtf(vx * vx + vy * vy + vz * vz);
    float inv = 1.0f / th;
    float ux = vx * inv, uy = vy * inv, uz = vz * inv;
    float s = sinf(th), c = cosf(th), C = 1.0f - c;
    R[0] = c + ux * ux * C;      R[1] = ux * uy * C - uz * s;  R[2] = ux * uz * C + uy * s;
    R[3] = uy * ux * C + uz * s; R[4] = c + uy * uy * C;       R[5] = uy * uz * C - ux * s;
    R[6] = uz * ux * C - uy * s; R[7] = uz * uy * C + ux * s;  R[8] = c + uz * uz * C;
}

__device__ __forceinline__ float softplus_stable(float t) {
    return fmaxf(t, 0.0f) + log1pf(expf(-fabsf(t)));
}

// ---------------- Kernel 1: half-k GEMV partials ----------------
__global__ void __launch_bounds__(THREADS)
so3_gemv_kernel(const float* __restrict__ x,
                const float* __restrict__ Wmu, const float* __restrict__ Wd,
                const float* __restrict__ Wl, int B)
{
    extern __shared__ unsigned char smem_raw[];
    u64*   wpkT = (u64*)smem_raw;                        // [j][HPAIR] for this half
    float* xs   = (float*)(smem_raw + 9 * HPAIR * 8);    // [STAGES][4 warps][64 rows][16]

    const int tid  = threadIdx.x;
    const int w    = tid >> 5;
    const int lane = tid & 31;
    const int half = blockIdx.x & 1;
    const int row0 = (blockIdx.x >> 1) * TILE_R;
    const int kbase = half * KHALF;

    // Rows: warp w owns row0 + w*64 + [0,64); thread handles lane, lane+32.
    const int ra = row0 + w * 64 + lane;
    const int rb = ra + 32;

    // Staging map: 64 rows x 4 quads = 256 16B segs, 8 per lane.
    // Lane covers rows a+8i (i=0..7), logical quad cf; stored at swizzled
    // column cf ^ ((a>>1)&3)  (row-swizzle invariant under +8: (a+8i)>>1&3 == (a>>1)&3).
    const int a  = lane >> 2;
    const int cf = lane & 3;
    const int scol = cf ^ ((a >> 1) & 3);
    const unsigned sA = (unsigned)(w * (WARP_FLOATS * 4) + a * 64 + scol * 16);
    int grA = row0 + w * 64 + a;   if (grA > B - 1) grA = B - 1;
    const float* gA = x + (size_t)grA * D_IN + kbase + cf * 4;

    const unsigned xs_base = (unsigned)__cvta_generic_to_shared(xs);

    // Prologue cp.async (chunks 0,1) before weight staging so loads fly early.
#pragma unroll
    for (int s = 0; s < STAGES - 1; s++) {
        unsigned base = xs_base + (unsigned)(s * XS_FLOATS * 4);
        const float* pA = gA + s * KC;
#pragma unroll
        for (int i = 0; i < 8; i++)   // rows a + 8i
            cp_async16(base + sA + (unsigned)(i * 8 * 64), pA + (size_t)(8 * i) * D_IN);
        cp_commit();
    }

    // Stage this half's weights transposed: wpkT[j*HPAIR + t] = pair k2 = half*HPAIR + t.
    for (int i = tid; i < 9 * HPAIR; i += THREADS) {
        int j = i / HPAIR, t = i - j * HPAIR;
        int k2 = half * HPAIR + t;
        const float* W;
        int c;
        if (j < 3)      { W = Wmu; c = j; }
        else if (j < 6) { W = Wd;  c = j - 3; }
        else            { W = Wl;  c = j - 6; }
        wpkT[i] = pack2(W[(2 * k2) * 3 + c], W[(2 * k2 + 1) * 3 + c]);
    }
    __syncthreads();   // weights visible; mainloop is barrier-free (warp-autonomous)

    u64 accA[9], accB[9];
#pragma unroll
    for (int j = 0; j < 9; j++) { accA[j] = 0ull; accB[j] = 0ull; }

    // Compute-side swizzle: thread reads rows r=lane and r=lane+32; both share
    // sw = (lane>>1)&3 ((lane+32)>>1&3 == sw).
    const int sw = (lane >> 1) & 3;
    const unsigned cA0 = (unsigned)(w * (WARP_FLOATS * 4) + lane * 64);
    int slot  = 0;
    int pslot = STAGES - 1;

#pragma unroll 1
    for (int ch = 0; ch < NCHUNK; ch++) {
        // Exact wait: chunk ch's group complete. At the final chunk it is the
        // newest group -> drain fully (tail-race fix).
        if (ch < NCHUNK - 1) cp_wait1(); else cp_wait0();
        __syncwarp();

        if (ch + STAGES - 1 < NCHUNK) {
            unsigned base = xs_base + (unsigned)(pslot * XS_FLOATS * 4);
            const float* pA = gA + (ch + STAGES - 1) * KC;
#pragma unroll
            for (int i = 0; i < 8; i++)
                cp_async16(base + sA + (unsigned)(i * 8 * 64), pA + (size_t)(8 * i) * D_IN);
            cp_commit();
        }

        const unsigned stage_b = (unsigned)(slot * XS_FLOATS * 4);
        const float* part = (const float*)((const unsigned char*)xs + stage_b);
        const u64*   wch  = wpkT + ch * (KC / 2);
#pragma unroll
        for (int p = 0; p < KC / 4; p++) {                 // 4 quads (logical order)
            int col = (p ^ sw) * 16;                       // swizzled byte column
            ulonglong2 xav = *(const ulonglong2*)((const unsigned char*)part + cA0 + col);
            ulonglong2 xbv = *(const ulonglong2*)((const unsigned char*)part + cA0 + 32 * 64 + col);
#pragma unroll
            for (int j = 0; j < 9; j++) {
                ulonglong2 wv = *(const ulonglong2*)&wch[j * HPAIR + 2 * p];  // broadcast
                ffma2(accA[j], xav.x, wv.x);
                ffma2(accB[j], xbv.x, wv.x);
                ffma2(accA[j], xav.y, wv.y);
                ffma2(accB[j], xbv.y, wv.y);
            }
        }

        slot  = (slot  + 1 == STAGES) ? 0 : slot  + 1;
        pslot = (pslot + 1 == STAGES) ? 0 : pslot + 1;
    }

    // Write partials: scratch[half][j][row], coalesced STG.32 per j.
    float* sc = g_scratch + (size_t)half * 9 * B;
    if (ra < B) {
#pragma unroll
        for (int j = 0; j < 9; j++) {
            float lo, hi;
            unpack2(accA[j], lo, hi);
            sc[(size_t)j * B + ra] = lo + hi;
        }
    }
    if (rb < B) {
#pragma unroll
        for (int j = 0; j < 9; j++) {
            float lo, hi;
            unpack2(accB[j], lo, hi);
            sc[(size_t)j * B + rb] = lo + hi;
        }
    }
}

// ---------------- Kernel 2: combine halves + Rodrigues epilogue ----------------
__global__ void __launch_bounds__(256)
so3_epilogue_kernel(const float* __restrict__ eps,
                    const float* __restrict__ bmu, const float* __restrict__ bd,
                    const float* __restrict__ bl,
                    float* __restrict__ out, int B, int n)
{
    const int row = blockIdx.x * 256 + threadIdx.x;
    if (row >= B) return;

    float s[9];
#pragma unroll
    for (int j = 0; j < 9; j++)
        s[j] = g_scratch[(size_t)j * B + row] + g_scratch[(size_t)(9 + j) * B + row];

    float m0 = s[0] + bmu[0], m1 = s[1] + bmu[1], m2 = s[2] + bmu[2];
    float sd0 = sqrtf(softplus_stable(s[3] + bd[0]));
    float sd1 = sqrtf(softplus_stable(s[4] + bd[1]));
    float sd2 = sqrtf(softplus_stable(s[5] + bd[2]));
    float l0 = s[6] + bl[0], l1 = s[7] + bl[1], l2 = s[8] + bl[2];

    float Rm[9];
    rodrigues(m0, m1, m2, Rm);

    for (int jn = 0; jn < n; jn++) {
        size_t base = (size_t)(jn * B + row) * 3;
        float e0 = eps[base + 0], e1 = eps[base + 1], e2 = eps[base + 2];
        float a0 = sd0 * e0, a1 = sd1 * e1, a2 = sd2 * e2;
        float v0 = a0;
        float v1 = l0 * a0 + a1;
        float v2 = l1 * a0 + l2 * a1 + a2;

        float Rv[9];
        rodrigues(v0, v1, v2, Rv);

        float* o = out + (size_t)(jn * B + row) * 9;
#pragma unroll
        for (int i = 0; i < 3; i++) {
#pragma unroll
            for (int k = 0; k < 3; k++) {
                o[i * 3 + k] = Rm[i * 3 + 0] * Rv[0 * 3 + k]
                             + Rm[i * 3 + 1] * Rv[1 * 3 + k]
                             + Rm[i * 3 + 2] * Rv[2 * 3 + k];
            }
        }
    }
}

extern "C" void kernel_launch(void* const* d_in, const int* in_sizes, int n_in,
                              void* d_out, int out_size)
{
    const float* x   = (const float*)d_in[0];
    const float* eps = (const float*)d_in[1];
    const float* Wmu = (const float*)d_in[2];
    const float* bmu = (const float*)d_in[3];
    const float* Wd  = (const float*)d_in[4];
    const float* bd  = (const float*)d_in[5];
    const float* Wl  = (const float*)d_in[6];
    const float* bl  = (const float*)d_in[7];

    const int B = in_sizes[0] / D_IN;
    const int n = in_sizes[1] / (B * 3);

    cudaFuncSetAttribute(so3_gemv_kernel, cudaFuncAttributeMaxDynamicSharedMemorySize, SMEM_BYTES);

    const int grid1 = ((B + TILE_R - 1) / TILE_R) * 2;   // x2 k-halves
    so3_gemv_kernel<<<grid1, THREADS, SMEM_BYTES>>>(x, Wmu, Wd, Wl, B);

    const int grid2 = (B + 255) / 256;
    so3_epilogue_kernel<<<grid2, 256>>>(eps, bmu, bd, bl, (float*)d_out, B, n);
}